// round 16
// baseline (speedup 1.0000x reference)
#include <cuda_runtime.h>
#include <cuda_bf16.h>
#include <cstdint>

// Problem constants (fixed by the dataset): N=1,000,000 points, C=64 channels, K=64 grid
#define KGRID    64
#define NCELLS   (KGRID * KGRID * KGRID)   // 262144
#define NMAX     1000064
#define CAP      32                        // slots per cell; dataset max count ~18 (Poisson lam=3.8)

// Scratch in __device__ globals (no allocation allowed)
__device__ int g_counts[NCELLS];           // per-cell point count (atomic)
__device__ int g_slots[NCELLS * CAP];      // per-cell point-id slots (128B-aligned blocks)

__device__ __forceinline__ int cell_of(float x, float y, float z) {
    int ix = (int)floorf((x + 1.0f) * (KGRID * 0.5f));
    int iy = (int)floorf((y + 1.0f) * (KGRID * 0.5f));
    int iz = (int)floorf((z + 1.0f) * (KGRID * 0.5f));
    ix = min(max(ix, 0), KGRID - 1);
    iy = min(max(iy, 0), KGRID - 1);
    iz = min(max(iz, 0), KGRID - 1);
    return ix * (KGRID * KGRID) + iy * KGRID + iz;
}

// ---------------------------------------------------------------------------
// Build kernel — ONE pass (R15 win: replaces histogram+scan+reorder, ~8us).
// Each thread bins 4 points: pos = atomicAdd(count), slot[cell*CAP+pos] = id.
// 4 points per thread via three float4 loads (12 floats = 4 xyz triples).
// ---------------------------------------------------------------------------
__global__ void build_kernel(const float4* __restrict__ pts4, int n4, int n) {
    int i4 = blockIdx.x * blockDim.x + threadIdx.x;
    if (i4 >= n4) return;
    int base = i4 * 4;

    if (base + 4 <= n) {
        float4 a = pts4[i4 * 3 + 0];   // x0 y0 z0 x1
        float4 b = pts4[i4 * 3 + 1];   // y1 z1 x2 y2
        float4 c = pts4[i4 * 3 + 2];   // z2 x3 y3 z3
        int c0 = cell_of(a.x, a.y, a.z);
        int c1 = cell_of(a.w, b.x, b.y);
        int c2 = cell_of(b.z, b.w, c.x);
        int c3 = cell_of(c.y, c.z, c.w);
        int p0 = atomicAdd(&g_counts[c0], 1);
        int p1 = atomicAdd(&g_counts[c1], 1);
        int p2 = atomicAdd(&g_counts[c2], 1);
        int p3 = atomicAdd(&g_counts[c3], 1);
        if (p0 < CAP) g_slots[c0 * CAP + p0] = base + 0;
        if (p1 < CAP) g_slots[c1 * CAP + p1] = base + 1;
        if (p2 < CAP) g_slots[c2 * CAP + p2] = base + 2;
        if (p3 < CAP) g_slots[c3 * CAP + p3] = base + 3;
    } else {
        const float* p = (const float*)pts4;
        for (int i = base; i < n; i++) {
            int cc = cell_of(p[3 * i], p[3 * i + 1], p[3 * i + 2]);
            int pos = atomicAdd(&g_counts[cc], 1);
            if (pos < CAP) g_slots[cc * CAP + pos] = i;
        }
    }
}

// ---------------------------------------------------------------------------
// Gather + mean — R11 body structure (R13 lesson: don't perturb), but the
// slot indices are fetched with int4 loads: one LDG.128 per 4 ids instead of
// four LDG.32 (R15 post-mortem: scalar slot loads cost ~13us). Tail uses one
// aligned int4 and consumes only valid components — feat loads stay EXACT
// (R7 lesson). 16 threads per cell; .cs feat stream; 32 regs / 8 CTAs per SM.
// ---------------------------------------------------------------------------
__global__ void __launch_bounds__(256, 8)
gather_kernel(const float4* __restrict__ feat4,
              float4* __restrict__ out) {
    int gid = blockIdx.x * blockDim.x + threadIdx.x;   // NCELLS*16 threads
    int cell = gid >> 4;
    int q    = gid & 15;
    int cnt  = __ldg(&g_counts[cell]);
    int m    = min(cnt, CAP);            // guard (overflow statistically impossible)
    const int4* slot4 = (const int4*)(g_slots + cell * CAP);
    const float4* fq  = feat4 + q;

    float4 acc = make_float4(0.f, 0.f, 0.f, 0.f);
    int j = 0;
    for (; j + 4 <= m; j += 4) {
        int4 s = slot4[j >> 2];          // 4 point-ids in one LDG.128
        float4 a = __ldcs(fq + (size_t)s.x * 16);
        float4 b = __ldcs(fq + (size_t)s.y * 16);
        float4 c = __ldcs(fq + (size_t)s.z * 16);
        float4 d = __ldcs(fq + (size_t)s.w * 16);
        acc.x += a.x + b.x + c.x + d.x;
        acc.y += a.y + b.y + c.y + d.y;
        acc.z += a.z + b.z + c.z + d.z;
        acc.w += a.w + b.w + c.w + d.w;
    }
    int r = m - j;                        // 0..3 remaining
    if (r > 0) {
        int4 s = slot4[j >> 2];          // aligned, in-bounds (block is 128B)
        float4 a = __ldcs(fq + (size_t)s.x * 16);
        acc.x += a.x; acc.y += a.y; acc.z += a.z; acc.w += a.w;
        if (r > 1) {
            float4 b = __ldcs(fq + (size_t)s.y * 16);
            acc.x += b.x; acc.y += b.y; acc.z += b.z; acc.w += b.w;
        }
        if (r > 2) {
            float4 c = __ldcs(fq + (size_t)s.z * 16);
            acc.x += c.x; acc.y += c.y; acc.z += c.z; acc.w += c.w;
        }
    }

    float inv = (cnt > 0) ? (1.0f / (float)cnt) : 1.0f;
    acc.x *= inv; acc.y *= inv; acc.z *= inv; acc.w *= inv;
    out[(size_t)cell * 16 + q] = acc;   // empty cells correctly write 0
}

// ---------------------------------------------------------------------------
// Launcher
// inputs: d_in[0] = point_feat (N*64 f32), d_in[1] = points (N*3 f32),
//         d_in[2] = k (int, =64). out: (64,64,64,64) f32
// ---------------------------------------------------------------------------
extern "C" void kernel_launch(void* const* d_in, const int* in_sizes, int n_in,
                              void* d_out, int out_size) {
    const float4* pts4  = (const float4*)d_in[1];
    const float4* feat4 = (const float4*)d_in[0];
    float4* out = (float4*)d_out;

    int n  = in_sizes[1] / 3;        // number of points
    int n4 = (n + 3) / 4;            // 4 points per build thread

    // zero the counts scratch (1 MB)
    void* counts_ptr = nullptr;
    cudaGetSymbolAddress(&counts_ptr, g_counts);
    cudaMemsetAsync(counts_ptr, 0, NCELLS * sizeof(int), 0);

    const int T = 256;
    build_kernel<<<(n4 + T - 1) / T, T>>>(pts4, n4, n);
    gather_kernel<<<(NCELLS * 16) / T, T>>>(feat4, out);
}

// round 17
// speedup vs baseline: 1.0092x; 1.0092x over previous
#include <cuda_runtime.h>
#include <cuda_bf16.h>
#include <cstdint>

// Problem constants (fixed by the dataset): N=1,000,000 points, C=64 channels, K=64 grid
#define KGRID    64
#define NCELLS   (KGRID * KGRID * KGRID)   // 262144
#define NMAX     1000064
#define CAP      16                        // slots per cell (64B block). Poisson(3.8) max ~16-18:
                                           // rare overflow handled exactly via the overflow list.
#define OVF_MAX  4096                      // overflow list capacity (expect < ~10 entries)

// Scratch in __device__ globals (no allocation allowed)
__device__ int  g_counts[NCELLS];          // per-cell point count (atomic)
__device__ int  g_slots[NCELLS * CAP];     // per-cell point-id slots (64B-aligned blocks)
__device__ int  g_ovf_n;                   // overflow entry count
__device__ int2 g_ovf[OVF_MAX];            // overflow entries {cell, point_id}

__device__ __forceinline__ int cell_of(float x, float y, float z) {
    int ix = (int)floorf((x + 1.0f) * (KGRID * 0.5f));
    int iy = (int)floorf((y + 1.0f) * (KGRID * 0.5f));
    int iz = (int)floorf((z + 1.0f) * (KGRID * 0.5f));
    ix = min(max(ix, 0), KGRID - 1);
    iy = min(max(iy, 0), KGRID - 1);
    iz = min(max(iz, 0), KGRID - 1);
    return ix * (KGRID * KGRID) + iy * KGRID + iz;
}

// ---------------------------------------------------------------------------
// Build kernel — ONE pass (R15 win). Each thread bins 4 points:
// pos = atomicAdd(count); pos < CAP -> slot write, else -> overflow list.
// ---------------------------------------------------------------------------
__global__ void build_kernel(const float4* __restrict__ pts4, int n4, int n) {
    int i4 = blockIdx.x * blockDim.x + threadIdx.x;
    if (i4 >= n4) return;
    int base = i4 * 4;

    if (base + 4 <= n) {
        float4 a = pts4[i4 * 3 + 0];   // x0 y0 z0 x1
        float4 b = pts4[i4 * 3 + 1];   // y1 z1 x2 y2
        float4 c = pts4[i4 * 3 + 2];   // z2 x3 y3 z3
        int cc[4];
        cc[0] = cell_of(a.x, a.y, a.z);
        cc[1] = cell_of(a.w, b.x, b.y);
        cc[2] = cell_of(b.z, b.w, c.x);
        cc[3] = cell_of(c.y, c.z, c.w);
        #pragma unroll
        for (int j = 0; j < 4; j++) {
            int pos = atomicAdd(&g_counts[cc[j]], 1);
            if (pos < CAP) {
                g_slots[cc[j] * CAP + pos] = base + j;
            } else {
                int o = atomicAdd(&g_ovf_n, 1);
                if (o < OVF_MAX) g_ovf[o] = make_int2(cc[j], base + j);
            }
        }
    } else {
        const float* p = (const float*)pts4;
        for (int i = base; i < n; i++) {
            int cc = cell_of(p[3 * i], p[3 * i + 1], p[3 * i + 2]);
            int pos = atomicAdd(&g_counts[cc], 1);
            if (pos < CAP) {
                g_slots[cc * CAP + pos] = i;
            } else {
                int o = atomicAdd(&g_ovf_n, 1);
                if (o < OVF_MAX) g_ovf[o] = make_int2(cc, i);
            }
        }
    }
}

// ---------------------------------------------------------------------------
// Gather + mean — body identical to R16 except CAP (R16 post-mortem: the
// 32MB slot array blew the L2 working set; 16MB restores out-region
// residency). 16 threads per cell; int4 slot loads; exact .cs feat loads;
// 32 regs / 8 CTAs per SM.
// ---------------------------------------------------------------------------
__global__ void __launch_bounds__(256, 8)
gather_kernel(const float4* __restrict__ feat4,
              float4* __restrict__ out) {
    int gid = blockIdx.x * blockDim.x + threadIdx.x;   // NCELLS*16 threads
    int cell = gid >> 4;
    int q    = gid & 15;
    int cnt  = __ldg(&g_counts[cell]);
    int m    = min(cnt, CAP);
    const int4* slot4 = (const int4*)(g_slots + cell * CAP);
    const float4* fq  = feat4 + q;

    float4 acc = make_float4(0.f, 0.f, 0.f, 0.f);
    int j = 0;
    for (; j + 4 <= m; j += 4) {
        int4 s = slot4[j >> 2];          // 4 point-ids in one LDG.128
        float4 a = __ldcs(fq + (size_t)s.x * 16);
        float4 b = __ldcs(fq + (size_t)s.y * 16);
        float4 c = __ldcs(fq + (size_t)s.z * 16);
        float4 d = __ldcs(fq + (size_t)s.w * 16);
        acc.x += a.x + b.x + c.x + d.x;
        acc.y += a.y + b.y + c.y + d.y;
        acc.z += a.z + b.z + c.z + d.z;
        acc.w += a.w + b.w + c.w + d.w;
    }
    int r = m - j;                        // 0..3 remaining
    if (r > 0) {
        int4 s = slot4[j >> 2];          // aligned, in-bounds (block is 64B)
        float4 a = __ldcs(fq + (size_t)s.x * 16);
        acc.x += a.x; acc.y += a.y; acc.z += a.z; acc.w += a.w;
        if (r > 1) {
            float4 b = __ldcs(fq + (size_t)s.y * 16);
            acc.x += b.x; acc.y += b.y; acc.z += b.z; acc.w += b.w;
        }
        if (r > 2) {
            float4 c = __ldcs(fq + (size_t)s.z * 16);
            acc.x += c.x; acc.y += c.y; acc.z += c.z; acc.w += c.w;
        }
    }

    float inv = (cnt > 0) ? (1.0f / (float)cnt) : 1.0f;
    acc.x *= inv; acc.y *= inv; acc.z *= inv; acc.w *= inv;
    out[(size_t)cell * 16 + q] = acc;   // empty cells correctly write 0
}

// ---------------------------------------------------------------------------
// Overflow fixup — adds feat[p]/cnt for the (rare) points that didn't fit in
// their cell's slot block. Runs after gather; float atomics into out.
// Expected entries: < ~10, so this is launch-overhead only.
// ---------------------------------------------------------------------------
__global__ void fixup_kernel(const float4* __restrict__ feat4,
                             float* __restrict__ out) {
    int tot = min(g_ovf_n, OVF_MAX);
    int nwork = tot * 16;                               // 16 lanes per entry
    for (int e = blockIdx.x * blockDim.x + threadIdx.x; e < nwork;
         e += gridDim.x * blockDim.x) {
        int entry = e >> 4;
        int q     = e & 15;
        int2 oc   = g_ovf[entry];
        float inv = 1.0f / (float)g_counts[oc.x];
        float4 v  = feat4[(size_t)oc.y * 16 + q];
        float* dst = out + (size_t)oc.x * 64 + q * 4;
        atomicAdd(dst + 0, v.x * inv);
        atomicAdd(dst + 1, v.y * inv);
        atomicAdd(dst + 2, v.z * inv);
        atomicAdd(dst + 3, v.w * inv);
    }
}

// ---------------------------------------------------------------------------
// Launcher
// inputs: d_in[0] = point_feat (N*64 f32), d_in[1] = points (N*3 f32),
//         d_in[2] = k (int, =64). out: (64,64,64,64) f32
// ---------------------------------------------------------------------------
extern "C" void kernel_launch(void* const* d_in, const int* in_sizes, int n_in,
                              void* d_out, int out_size) {
    const float4* pts4  = (const float4*)d_in[1];
    const float4* feat4 = (const float4*)d_in[0];
    float4* out = (float4*)d_out;

    int n  = in_sizes[1] / 3;        // number of points
    int n4 = (n + 3) / 4;            // 4 points per build thread

    // zero the counts scratch (1 MB) and the overflow counter
    void* counts_ptr = nullptr;
    void* ovfn_ptr   = nullptr;
    cudaGetSymbolAddress(&counts_ptr, g_counts);
    cudaGetSymbolAddress(&ovfn_ptr,   g_ovf_n);
    cudaMemsetAsync(counts_ptr, 0, NCELLS * sizeof(int), 0);
    cudaMemsetAsync(ovfn_ptr,   0, sizeof(int), 0);

    const int T = 256;
    build_kernel<<<(n4 + T - 1) / T, T>>>(pts4, n4, n);
    gather_kernel<<<(NCELLS * 16) / T, T>>>(feat4, out);
    fixup_kernel<<<16, T>>>(feat4, (float*)out);
}